// round 10
// baseline (speedup 1.0000x reference)
#include <cuda_runtime.h>
#include <cuda_fp16.h>
#include <cstdint>
#include <math.h>

// Problem dims (fixed)
#define H_DIM 4096
#define I_DIM 11008
#define NTOK  4096

#define BKH 64                          // halves (k) per pipeline stage
#define S  3
#define LDSTR 72                        // halves per smem row (128B data + 16B pad)
#define TILE128 (128 * LDSTR)
#define TILE256 (256 * LDSTR)
#define NTHREADS 512
#define STG (TILE256 + TILE128)         // halves per stage (A 256 rows + B 128 rows)

// Device scratch — natural K-major fp16 layouts
__device__ __half g_x[(size_t)NTOK * H_DIM];
__device__ __half g_h[(size_t)NTOK * I_DIM];
__device__ __half g_wu[(size_t)I_DIM * H_DIM];
__device__ __half g_wg[(size_t)I_DIM * H_DIM];
__device__ __half g_wd[(size_t)H_DIM * I_DIM];
__device__ int    g_idx[NTOK];
__device__ int    g_zidx[NTOK];
__device__ int    g_count;

// ---------------------------------------------------------------------------
__device__ __forceinline__ uint32_t h2_as_u32(__half2 h) {
    return *reinterpret_cast<uint32_t*>(&h);
}
__device__ __forceinline__ void cp16(void* dst_smem, const void* src) {
    uint32_t d = (uint32_t)__cvta_generic_to_shared(dst_smem);
    asm volatile("cp.async.cg.shared.global [%0], [%1], 16;" :: "r"(d), "l"(src) : "memory");
}
#define CP_COMMIT() asm volatile("cp.async.commit_group;" ::: "memory")
#define CP_WAIT(n)  asm volatile("cp.async.wait_group %0;" :: "n"(n) : "memory")

__device__ __forceinline__ void mma16(float* d, const uint32_t* a, const uint32_t* b) {
    asm volatile(
        "mma.sync.aligned.m16n8k16.row.col.f32.f16.f16.f32 "
        "{%0,%1,%2,%3}, {%4,%5,%6,%7}, {%8,%9}, {%0,%1,%2,%3};"
        : "+f"(d[0]), "+f"(d[1]), "+f"(d[2]), "+f"(d[3])
        : "r"(a[0]), "r"(a[1]), "r"(a[2]), "r"(a[3]), "r"(b[0]), "r"(b[1]));
}
__device__ __forceinline__ void ldsm4(uint32_t addr, uint32_t* r) {
    asm volatile("ldmatrix.sync.aligned.m8n8.x4.shared.b16 {%0,%1,%2,%3}, [%4];"
                 : "=r"(r[0]), "=r"(r[1]), "=r"(r[2]), "=r"(r[3]) : "r"(addr));
}

// ---------------------------------------------------------------------------
// Compaction scan (single block): active list + inactive list
// ---------------------------------------------------------------------------
__global__ void compact_kernel(const int* __restrict__ mask) {
    __shared__ int warp_sums[32];
    const int tid = threadIdx.x, lane = tid & 31, warp = tid >> 5;
    int flags[4], cnt = 0;
#pragma unroll
    for (int j = 0; j < 4; ++j) {
        int f = (mask[tid * 4 + j] != 0) ? 1 : 0;
        flags[j] = f; cnt += f;
    }
    int v = cnt;
#pragma unroll
    for (int o = 1; o < 32; o <<= 1) { int n = __shfl_up_sync(~0u, v, o); if (lane >= o) v += n; }
    if (lane == 31) warp_sums[warp] = v;
    __syncthreads();
    if (warp == 0) {
        int s = warp_sums[lane];
#pragma unroll
        for (int o = 1; o < 32; o <<= 1) { int n = __shfl_up_sync(~0u, s, o); if (lane >= o) s += n; }
        warp_sums[lane] = s;
    }
    __syncthreads();
    int base = v - cnt + (warp > 0 ? warp_sums[warp - 1] : 0);
#pragma unroll
    for (int j = 0; j < 4; ++j) {
        int t = tid * 4 + j;
        if (flags[j]) g_idx[base++] = t;
        else          g_zidx[t - base] = t;
    }
    if (tid == 1023) g_count = base;
}

// ---------------------------------------------------------------------------
__device__ __forceinline__ uint4 cvt8(float4 f0, float4 f1) {
    uint4 o;
    o.x = h2_as_u32(__floats2half2_rn(f0.x, f0.y));
    o.y = h2_as_u32(__floats2half2_rn(f0.z, f0.w));
    o.z = h2_as_u32(__floats2half2_rn(f1.x, f1.y));
    o.w = h2_as_u32(__floats2half2_rn(f1.z, f1.w));
    return o;
}

__global__ void cvt_kernel(const float4* __restrict__ src, uint4* __restrict__ dst, int ngroups) {
    int i = blockIdx.x * blockDim.x + threadIdx.x;
    int stride = gridDim.x * blockDim.x;
    for (; i < ngroups; i += stride) dst[i] = cvt8(src[2 * i], src[2 * i + 1]);
}

// Gather active rows into g_x (fp16); zero-pad to 256-row boundary.
__global__ void gather_kernel(const float4* __restrict__ hidden) {
    int row = blockIdx.x;
    int c = g_count;
    int cpad = (c + 255) & ~255;
    if (row >= cpad) return;
    uint4* dst = (uint4*)(g_x + (size_t)row * H_DIM);
    if (row < c) {
        const float4* src = hidden + (size_t)g_idx[row] * (H_DIM / 4);
        for (int i = threadIdx.x; i < H_DIM / 8; i += 256)
            dst[i] = cvt8(src[2 * i], src[2 * i + 1]);
    } else {
        uint4 z = make_uint4(0, 0, 0, 0);
        for (int i = threadIdx.x; i < H_DIM / 8; i += 256) dst[i] = z;
    }
}

__global__ void zero_rows_kernel(float4* __restrict__ out) {
    int nz = NTOK - g_count;
    if ((int)blockIdx.x >= nz) return;
    float4* p = out + (size_t)g_zidx[blockIdx.x] * (H_DIM / 4);
    float4 z = make_float4(0.f, 0.f, 0.f, 0.f);
    for (int i = threadIdx.x; i < H_DIM / 4; i += 256) p[i] = z;
}

// ---------------------------------------------------------------------------
// GEMM template: CTA 256m x 128n, 16 warps @ 64x32 (4m x 4n), S=3, BK=64.
// A-fragment double-buffered; B fragments just-in-time.
// MODE 0: A=g_x, B=g_wg, K=H    -> g_h = fp16(silu(acc))
// MODE 1: A=g_x, B=g_wu, K=H    -> g_h = fp16(acc * g_h)      (RMW)
// MODE 2: A=g_h, B=g_wd, K=I    -> out[g_idx[m]] = acc        (scatter fp32)
// ---------------------------------------------------------------------------
template <int MODE>
__global__ __launch_bounds__(NTHREADS, 1)
void gemm_kernel(const __half* __restrict__ Bw, float* __restrict__ out, int K)
{
    const int Mc = g_count;
    const int m0 = blockIdx.x * 256;
    if (m0 >= Mc) return;
    const int n0 = blockIdx.y * 128;

    extern __shared__ __half smh[];
    const uint32_t smem_b = (uint32_t)__cvta_generic_to_shared(smh);

    const int tid  = threadIdx.x;
    const int lane = tid & 31;
    const int wid  = tid >> 5;      // 0..15
    const int wm   = wid >> 2;      // 0..3 -> m offset 64
    const int wn   = wid & 3;       // 0..3 -> n offset 32
    const int g    = lane >> 2;
    const int c    = lane & 3;

    const int nk = K / BKH;

    // ldmatrix lane-address offsets (bytes via *2 later), kg=0
    uint32_t a_off[4], b_off[2];
    {
        const int ar = wm * 64 + ((lane >> 3) & 1) * 8 + (lane & 7);
        const int ac = ((lane >> 4) & 1) * 8;
#pragma unroll
        for (int i = 0; i < 4; ++i) a_off[i] = (uint32_t)((ar + i * 16) * LDSTR + ac);
        const int br = wn * 32 + ((lane >> 4) & 1) * 8 + (lane & 7);
        const int bc = ((lane >> 3) & 1) * 8;
#pragma unroll
        for (int p = 0; p < 2; ++p)
            b_off[p] = (uint32_t)(TILE256 + (br + p * 16) * LDSTR + bc);
    }

    const __half* srcA = (MODE == 2 ? g_h : g_x) + (size_t)m0 * K;
    const __half* srcB = Bw + (size_t)n0 * K;

#define ISSUE(t) do {                                                          \
        __half* st = smh + ((t) % S) * STG;                                    \
        const size_t kof = (size_t)(t) * BKH;                                  \
        _Pragma("unroll")                                                      \
        for (int ii = 0; ii < 4; ++ii) {                                       \
            int id = tid + ii * 512;                                           \
            int row = id >> 3, ch = id & 7;                                    \
            cp16(st + row * LDSTR + ch * 8,                                    \
                 srcA + (size_t)row * K + kof + ch * 8);                       \
        }                                                                      \
        _Pragma("unroll")                                                      \
        for (int ii = 0; ii < 2; ++ii) {                                       \
            int id = tid + ii * 512;                                           \
            int row = id >> 3, ch = id & 7;                                    \
            cp16(st + TILE256 + row * LDSTR + ch * 8,                          \
                 srcB + (size_t)row * K + kof + ch * 8);                       \
        }                                                                      \
    } while (0)

#pragma unroll
    for (int t = 0; t < S - 1; ++t) { ISSUE(t); CP_COMMIT(); }

    float acc[4][4][4];
#pragma unroll
    for (int i = 0; i < 4; ++i)
#pragma unroll
        for (int j = 0; j < 4; ++j)
#pragma unroll
            for (int r = 0; r < 4; ++r) acc[i][j][r] = 0.f;

    uint32_t af[2][4][4];   // A-fragment double buffer

    for (int t = 0; t < nk; ++t) {
        CP_WAIT(S - 2);
        __syncthreads();
        if (t + S - 1 < nk) ISSUE(t + S - 1);
        CP_COMMIT();

        const uint32_t sb = smem_b + (uint32_t)((t % S) * STG) * 2;

        // prefetch A fragments for kg=0
#pragma unroll
        for (int i = 0; i < 4; ++i) ldsm4(sb + 2 * a_off[i], af[0][i]);

#pragma unroll
        for (int kg = 0; kg < 4; ++kg) {
            const int cur = kg & 1;
            const uint32_t kb = (uint32_t)kg * 32;

            // B fragments just-in-time
            uint32_t bf[4][2];
#pragma unroll
            for (int p = 0; p < 2; ++p) {
                uint32_t rb[4];
                ldsm4(sb + 2 * b_off[p] + kb, rb);
                bf[2 * p][0] = rb[0]; bf[2 * p][1] = rb[1];
                bf[2 * p + 1][0] = rb[2]; bf[2 * p + 1][1] = rb[3];
            }
            // prefetch next kg's A fragments while bf latency drains
            if (kg < 3) {
#pragma unroll
                for (int i = 0; i < 4; ++i)
                    ldsm4(sb + 2 * a_off[i] + kb + 32, af[cur ^ 1][i]);
            }
#pragma unroll
            for (int i = 0; i < 4; ++i)
#pragma unroll
                for (int j = 0; j < 4; ++j)
                    mma16(acc[i][j], af[cur][i], bf[j]);
        }
    }
#undef ISSUE

    // ---- epilogue ----
#pragma unroll
    for (int i = 0; i < 4; ++i) {
#pragma unroll
        for (int h = 0; h < 2; ++h) {
            const int gm = m0 + wm * 64 + i * 16 + g + h * 8;
            if (MODE == 0) {
                __half* rowp = g_h + (size_t)gm * I_DIM;
#pragma unroll
                for (int j = 0; j < 4; ++j) {
                    const int gn = n0 + wn * 32 + j * 8 + 2 * c;
                    float v0 = acc[i][j][h * 2 + 0], v1 = acc[i][j][h * 2 + 1];
                    float s0 = v0 / (1.f + __expf(-v0));
                    float s1 = v1 / (1.f + __expf(-v1));
                    *(__half2*)(rowp + gn) = __floats2half2_rn(s0, s1);
                }
            } else if (MODE == 1) {
                __half* rowp = g_h + (size_t)gm * I_DIM;
#pragma unroll
                for (int j = 0; j < 4; ++j) {
                    const int gn = n0 + wn * 32 + j * 8 + 2 * c;
                    float2 fg = __half22float2(*(__half2*)(rowp + gn));
                    float v0 = acc[i][j][h * 2 + 0], v1 = acc[i][j][h * 2 + 1];
                    *(__half2*)(rowp + gn) = __floats2half2_rn(v0 * fg.x, v1 * fg.y);
                }
            } else {
                if (gm < Mc) {
                    float* rowp = out + (size_t)g_idx[gm] * H_DIM;
#pragma unroll
                    for (int j = 0; j < 4; ++j) {
                        const int gn = n0 + wn * 32 + j * 8 + 2 * c;
                        *(float2*)(rowp + gn) =
                            make_float2(acc[i][j][h * 2 + 0], acc[i][j][h * 2 + 1]);
                    }
                }
            }
        }
    }
}

// ---------------------------------------------------------------------------
extern "C" void kernel_launch(void* const* d_in, const int* in_sizes, int n_in,
                              void* d_out, int out_size)
{
    const float* hidden = (const float*)d_in[0];
    const float* w_up   = (const float*)d_in[1];
    const float* w_gate = (const float*)d_in[2];
    const float* w_down = (const float*)d_in[3];
    const int*   mask   = (const int*)d_in[4];
    float* out = (float*)d_out;

    const int SMEM = S * STG * sizeof(__half);   // 165888
    cudaFuncSetAttribute(gemm_kernel<0>, cudaFuncAttributeMaxDynamicSharedMemorySize, SMEM);
    cudaFuncSetAttribute(gemm_kernel<1>, cudaFuncAttributeMaxDynamicSharedMemorySize, SMEM);
    cudaFuncSetAttribute(gemm_kernel<2>, cudaFuncAttributeMaxDynamicSharedMemorySize, SMEM);

    void *d_wu, *d_wg, *d_wd;
    cudaGetSymbolAddress(&d_wu, g_wu);
    cudaGetSymbolAddress(&d_wg, g_wg);
    cudaGetSymbolAddress(&d_wd, g_wd);

    compact_kernel<<<1, 1024>>>(mask);
    gather_kernel<<<NTOK, 256>>>((const float4*)hidden);

    const int wg_groups = (I_DIM * H_DIM) / 8;
    cvt_kernel<<<4096, 256>>>((const float4*)w_gate, (uint4*)d_wg, wg_groups);
    cvt_kernel<<<4096, 256>>>((const float4*)w_up,   (uint4*)d_wu, wg_groups);
    cvt_kernel<<<4096, 256>>>((const float4*)w_down, (uint4*)d_wd, wg_groups);

    zero_rows_kernel<<<NTOK, 256>>>((float4*)out);

    dim3 blk(NTHREADS);
    gemm_kernel<0><<<dim3(NTOK / 256, I_DIM / 128), blk, SMEM>>>((const __half*)d_wg, nullptr, H_DIM);
    gemm_kernel<1><<<dim3(NTOK / 256, I_DIM / 128), blk, SMEM>>>((const __half*)d_wu, nullptr, H_DIM);
    gemm_kernel<2><<<dim3(NTOK / 256, H_DIM / 128), blk, SMEM>>>((const __half*)d_wd, out, I_DIM);
}

// round 11
// speedup vs baseline: 1.0905x; 1.0905x over previous
#include <cuda_runtime.h>
#include <cuda_fp16.h>
#include <cstdint>
#include <math.h>

// Problem dims (fixed)
#define H_DIM 4096
#define I_DIM 11008
#define NTOK  4096

#define BKH 64                          // halves (k) per pipeline stage
#define S  4
#define LDSTR 72                        // halves per smem row (128B data + 16B pad)
#define TILE128 (128 * LDSTR)
#define TILE256 (256 * LDSTR)
#define NTHREADS 512

// Device scratch — natural K-major fp16 layouts
__device__ __half g_x[(size_t)NTOK * H_DIM];
__device__ __half g_h[(size_t)NTOK * I_DIM];
__device__ __half g_wu[(size_t)I_DIM * H_DIM];
__device__ __half g_wg[(size_t)I_DIM * H_DIM];
__device__ __half g_wd[(size_t)H_DIM * I_DIM];
__device__ int    g_idx[NTOK];
__device__ int    g_zidx[NTOK];
__device__ int    g_count;

// ---------------------------------------------------------------------------
__device__ __forceinline__ uint32_t h2_as_u32(__half2 h) {
    return *reinterpret_cast<uint32_t*>(&h);
}
__device__ __forceinline__ void cp16(void* dst_smem, const void* src) {
    uint32_t d = (uint32_t)__cvta_generic_to_shared(dst_smem);
    asm volatile("cp.async.cg.shared.global [%0], [%1], 16;" :: "r"(d), "l"(src) : "memory");
}
#define CP_COMMIT() asm volatile("cp.async.commit_group;" ::: "memory")
#define CP_WAIT(n)  asm volatile("cp.async.wait_group %0;" :: "n"(n) : "memory")

__device__ __forceinline__ void mma16(float* d, const uint32_t* a, const uint32_t* b) {
    asm volatile(
        "mma.sync.aligned.m16n8k16.row.col.f32.f16.f16.f32 "
        "{%0,%1,%2,%3}, {%4,%5,%6,%7}, {%8,%9}, {%0,%1,%2,%3};"
        : "+f"(d[0]), "+f"(d[1]), "+f"(d[2]), "+f"(d[3])
        : "r"(a[0]), "r"(a[1]), "r"(a[2]), "r"(a[3]), "r"(b[0]), "r"(b[1]));
}
__device__ __forceinline__ void ldsm4(uint32_t addr, uint32_t* r) {
    asm volatile("ldmatrix.sync.aligned.m8n8.x4.shared.b16 {%0,%1,%2,%3}, [%4];"
                 : "=r"(r[0]), "=r"(r[1]), "=r"(r[2]), "=r"(r[3]) : "r"(addr));
}

// ---------------------------------------------------------------------------
// Compaction scan (single block): active list + inactive list
// ---------------------------------------------------------------------------
__global__ void compact_kernel(const int* __restrict__ mask) {
    __shared__ int warp_sums[32];
    const int tid = threadIdx.x, lane = tid & 31, warp = tid >> 5;
    int flags[4], cnt = 0;
#pragma unroll
    for (int j = 0; j < 4; ++j) {
        int f = (mask[tid * 4 + j] != 0) ? 1 : 0;
        flags[j] = f; cnt += f;
    }
    int v = cnt;
#pragma unroll
    for (int o = 1; o < 32; o <<= 1) { int n = __shfl_up_sync(~0u, v, o); if (lane >= o) v += n; }
    if (lane == 31) warp_sums[warp] = v;
    __syncthreads();
    if (warp == 0) {
        int s = warp_sums[lane];
#pragma unroll
        for (int o = 1; o < 32; o <<= 1) { int n = __shfl_up_sync(~0u, s, o); if (lane >= o) s += n; }
        warp_sums[lane] = s;
    }
    __syncthreads();
    int base = v - cnt + (warp > 0 ? warp_sums[warp - 1] : 0);
#pragma unroll
    for (int j = 0; j < 4; ++j) {
        int t = tid * 4 + j;
        if (flags[j]) g_idx[base++] = t;
        else          g_zidx[t - base] = t;
    }
    if (tid == 1023) g_count = base;
}

// ---------------------------------------------------------------------------
__device__ __forceinline__ uint4 cvt8(float4 f0, float4 f1) {
    uint4 o;
    o.x = h2_as_u32(__floats2half2_rn(f0.x, f0.y));
    o.y = h2_as_u32(__floats2half2_rn(f0.z, f0.w));
    o.z = h2_as_u32(__floats2half2_rn(f1.x, f1.y));
    o.w = h2_as_u32(__floats2half2_rn(f1.z, f1.w));
    return o;
}

// One launch converts all three weight matrices.
__global__ void cvt3_kernel(const float4* __restrict__ s0, uint4* __restrict__ d0,
                            const float4* __restrict__ s1, uint4* __restrict__ d1,
                            const float4* __restrict__ s2, uint4* __restrict__ d2,
                            int ngroups) {
    int i = blockIdx.x * blockDim.x + threadIdx.x;
    int stride = gridDim.x * blockDim.x;
    const int total = 3 * ngroups;
    for (; i < total; i += stride) {
        int sel = i / ngroups;
        int k = i - sel * ngroups;
        const float4* s = (sel == 0) ? s0 : (sel == 1) ? s1 : s2;
        uint4* d = (sel == 0) ? d0 : (sel == 1) ? d1 : d2;
        d[k] = cvt8(s[2 * k], s[2 * k + 1]);
    }
}

// Gather active rows into g_x (fp16); zero-pad to 128-row boundary.
__global__ void gather_kernel(const float4* __restrict__ hidden) {
    int row = blockIdx.x;
    int c = g_count;
    int cpad = (c + 127) & ~127;
    if (row >= cpad) return;
    uint4* dst = (uint4*)(g_x + (size_t)row * H_DIM);
    if (row < c) {
        const float4* src = hidden + (size_t)g_idx[row] * (H_DIM / 4);
        for (int i = threadIdx.x; i < H_DIM / 8; i += 256)
            dst[i] = cvt8(src[2 * i], src[2 * i + 1]);
    } else {
        uint4 z = make_uint4(0, 0, 0, 0);
        for (int i = threadIdx.x; i < H_DIM / 8; i += 256) dst[i] = z;
    }
}

__global__ void zero_rows_kernel(float4* __restrict__ out) {
    int nz = NTOK - g_count;
    if ((int)blockIdx.x >= nz) return;
    float4* p = out + (size_t)g_zidx[blockIdx.x] * (H_DIM / 4);
    float4 z = make_float4(0.f, 0.f, 0.f, 0.f);
    for (int i = threadIdx.x; i < H_DIM / 4; i += 256) p[i] = z;
}

// ---------------------------------------------------------------------------
// Fused up+gate GEMM. Block 128x128, 16 warps @ 32x32 (4m x 4n), dual acc.
// Per-warp kg skew breaks the post-barrier LDSM/MMA convoy.
// ---------------------------------------------------------------------------
#define STG_F (3 * TILE128)   // halves per stage

__global__ __launch_bounds__(NTHREADS, 1)
void fused_upgate_kernel()
{
    const int Mc = g_count;
    const int m0 = blockIdx.x * 128;
    if (m0 >= Mc) return;
    const int n0 = blockIdx.y * 128;

    extern __shared__ __half smh[];
    const uint32_t smem_b = (uint32_t)__cvta_generic_to_shared(smh);

    const int tid  = threadIdx.x;
    const int lane = tid & 31;
    const int wid  = tid >> 5;      // 0..15
    const int wm   = wid >> 2;      // 0..3
    const int wn   = wid & 3;       // 0..3
    const int g    = lane >> 2;
    const int c    = lane & 3;
    const int skew = wid & 3;

    const int nk = H_DIM / BKH;     // 64

    uint32_t a_off[2], u_off[2], gg_off[2];
    {
        const int ar = wm * 32 + ((lane >> 3) & 1) * 8 + (lane & 7);
        const int ac = ((lane >> 4) & 1) * 8;
#pragma unroll
        for (int i = 0; i < 2; ++i) a_off[i] = (uint32_t)((ar + i * 16) * LDSTR + ac);
        const int br = wn * 32 + ((lane >> 4) & 1) * 8 + (lane & 7);
        const int bc = ((lane >> 3) & 1) * 8;
#pragma unroll
        for (int p = 0; p < 2; ++p) {
            u_off[p]  = (uint32_t)(TILE128     + (br + p * 16) * LDSTR + bc);
            gg_off[p] = (uint32_t)(2 * TILE128 + (br + p * 16) * LDSTR + bc);
        }
    }

    const __half* srcA = g_x  + (size_t)m0 * H_DIM;
    const __half* srcU = g_wu + (size_t)n0 * H_DIM;
    const __half* srcG = g_wg + (size_t)n0 * H_DIM;

#define ISSUE_F(t) do {                                                        \
        __half* st = smh + ((t) % S) * STG_F;                                  \
        const size_t kof = (size_t)(t) * BKH;                                  \
        _Pragma("unroll")                                                      \
        for (int ii = 0; ii < 2; ++ii) {                                       \
            int id = tid + ii * 512;                                           \
            int row = id >> 3, ch = id & 7;                                    \
            cp16(st + row * LDSTR + ch * 8,                                    \
                 srcA + (size_t)row * H_DIM + kof + ch * 8);                   \
            cp16(st + TILE128 + row * LDSTR + ch * 8,                          \
                 srcU + (size_t)row * H_DIM + kof + ch * 8);                   \
            cp16(st + 2 * TILE128 + row * LDSTR + ch * 8,                      \
                 srcG + (size_t)row * H_DIM + kof + ch * 8);                   \
        }                                                                      \
    } while (0)

#pragma unroll
    for (int t = 0; t < S - 1; ++t) { ISSUE_F(t); CP_COMMIT(); }

    float acc_u[2][4][4], acc_g[2][4][4];
#pragma unroll
    for (int i = 0; i < 2; ++i)
#pragma unroll
        for (int j = 0; j < 4; ++j)
#pragma unroll
            for (int r = 0; r < 4; ++r) { acc_u[i][j][r] = 0.f; acc_g[i][j][r] = 0.f; }

    for (int t = 0; t < nk; ++t) {
        CP_WAIT(S - 2);
        __syncthreads();
        if (t + S - 1 < nk) ISSUE_F(t + S - 1);
        CP_COMMIT();

        const uint32_t sb = smem_b + (uint32_t)((t % S) * STG_F) * 2;

#pragma unroll
        for (int kgi = 0; kgi < 4; ++kgi) {
            const int kg = (kgi + skew) & 3;   // per-warp phase skew
            const uint32_t kb = (uint32_t)kg * 32;
            uint32_t af[2][4], uf[4][2], gf[4][2];
#pragma unroll
            for (int i = 0; i < 2; ++i) ldsm4(sb + 2 * a_off[i] + kb, af[i]);
#pragma unroll
            for (int p = 0; p < 2; ++p) {
                uint32_t ru[4], rg[4];
                ldsm4(sb + 2 * u_off[p] + kb, ru);
                ldsm4(sb + 2 * gg_off[p] + kb, rg);
                uf[2 * p][0] = ru[0]; uf[2 * p][1] = ru[1];
                uf[2 * p + 1][0] = ru[2]; uf[2 * p + 1][1] = ru[3];
                gf[2 * p][0] = rg[0]; gf[2 * p][1] = rg[1];
                gf[2 * p + 1][0] = rg[2]; gf[2 * p + 1][1] = rg[3];
            }
#pragma unroll
            for (int i = 0; i < 2; ++i)
#pragma unroll
                for (int j = 0; j < 4; ++j) {
                    mma16(acc_u[i][j], af[i], uf[j]);
                    mma16(acc_g[i][j], af[i], gf[j]);
                }
        }
    }
#undef ISSUE_F

    // epilogue: h = up*silu(gate) -> fp16
#pragma unroll
    for (int i = 0; i < 2; ++i) {
#pragma unroll
        for (int h = 0; h < 2; ++h) {
            const int gm = m0 + wm * 32 + i * 16 + g + h * 8;
            __half* rowp = g_h + (size_t)gm * I_DIM;
#pragma unroll
            for (int j = 0; j < 4; ++j) {
                const int gn = n0 + wn * 32 + j * 8 + 2 * c;
                float u0 = acc_u[i][j][h * 2 + 0], u1 = acc_u[i][j][h * 2 + 1];
                float gg0 = acc_g[i][j][h * 2 + 0], gg1 = acc_g[i][j][h * 2 + 1];
                float h0 = u0 * (gg0 / (1.f + __expf(-gg0)));
                float h1 = u1 * (gg1 / (1.f + __expf(-gg1)));
                *(__half2*)(rowp + gn) = __floats2half2_rn(h0, h1);
            }
        }
    }
}

// ---------------------------------------------------------------------------
// Down GEMM. Block 256x128, 16 warps @ 64x32 (4m x 4n), kg skew.
// ---------------------------------------------------------------------------
#define STG_D (TILE256 + TILE128)

__global__ __launch_bounds__(NTHREADS, 1)
void down_kernel(float* __restrict__ out)
{
    const int Mc = g_count;
    const int m0 = blockIdx.x * 256;
    if (m0 >= Mc) return;
    const int n0 = blockIdx.y * 128;

    extern __shared__ __half smh[];
    const uint32_t smem_b = (uint32_t)__cvta_generic_to_shared(smh);

    const int tid  = threadIdx.x;
    const int lane = tid & 31;
    const int wid  = tid >> 5;
    const int wm   = wid >> 2;      // 0..3
    const int wn   = wid & 3;       // 0..3
    const int g    = lane >> 2;
    const int c    = lane & 3;
    const int skew = wid & 3;

    const int nk = I_DIM / BKH;     // 172

    uint32_t a_off[4], b_off[2];
    {
        const int ar = wm * 64 + ((lane >> 3) & 1) * 8 + (lane & 7);
        const int ac = ((lane >> 4) & 1) * 8;
#pragma unroll
        for (int i = 0; i < 4; ++i) a_off[i] = (uint32_t)((ar + i * 16) * LDSTR + ac);
        const int br = wn * 32 + ((lane >> 4) & 1) * 8 + (lane & 7);
        const int bc = ((lane >> 3) & 1) * 8;
#pragma unroll
        for (int p = 0; p < 2; ++p)
            b_off[p] = (uint32_t)(TILE256 + (br + p * 16) * LDSTR + bc);
    }

    const __half* srcA = g_h  + (size_t)m0 * I_DIM;
    const __half* srcB = g_wd + (size_t)n0 * I_DIM;

#define ISSUE_D(t) do {                                                        \
        __half* st = smh + ((t) % S) * STG_D;                                  \
        const size_t kof = (size_t)(t) * BKH;                                  \
        _Pragma("unroll")                                                      \
        for (int ii = 0; ii < 4; ++ii) {                                       \
            int id = tid + ii * 512;                                           \
            int row = id >> 3, ch = id & 7;                                    \
            cp16(st + row * LDSTR + ch * 8,                                    \
                 srcA + (size_t)row * I_DIM + kof + ch * 8);                   \
        }                                                                      \
        _Pragma("unroll")                                                      \
        for (int ii = 0; ii < 2; ++ii) {                                       \
            int id = tid + ii * 512;                                           \
            int row = id >> 3, ch = id & 7;                                    \
            cp16(st + TILE256 + row * LDSTR + ch * 8,                          \
                 srcB + (size_t)row * I_DIM + kof + ch * 8);                   \
        }                                                                      \
    } while (0)

#pragma unroll
    for (int t = 0; t < S - 1; ++t) { ISSUE_D(t); CP_COMMIT(); }

    float acc[4][4][4];
#pragma unroll
    for (int i = 0; i < 4; ++i)
#pragma unroll
        for (int j = 0; j < 4; ++j)
#pragma unroll
            for (int r = 0; r < 4; ++r) acc[i][j][r] = 0.f;

    for (int t = 0; t < nk; ++t) {
        CP_WAIT(S - 2);
        __syncthreads();
        if (t + S - 1 < nk) ISSUE_D(t + S - 1);
        CP_COMMIT();

        const uint32_t sb = smem_b + (uint32_t)((t % S) * STG_D) * 2;

#pragma unroll
        for (int kgi = 0; kgi < 4; ++kgi) {
            const int kg = (kgi + skew) & 3;
            const uint32_t kb = (uint32_t)kg * 32;
            uint32_t af[4][4], bf[4][2];
#pragma unroll
            for (int i = 0; i < 4; ++i) ldsm4(sb + 2 * a_off[i] + kb, af[i]);
#pragma unroll
            for (int p = 0; p < 2; ++p) {
                uint32_t rb[4];
                ldsm4(sb + 2 * b_off[p] + kb, rb);
                bf[2 * p][0] = rb[0]; bf[2 * p][1] = rb[1];
                bf[2 * p + 1][0] = rb[2]; bf[2 * p + 1][1] = rb[3];
            }
#pragma unroll
            for (int i = 0; i < 4; ++i)
#pragma unroll
                for (int j = 0; j < 4; ++j)
                    mma16(acc[i][j], af[i], bf[j]);
        }
    }
#undef ISSUE_D

    // epilogue: scatter
#pragma unroll
    for (int i = 0; i < 4; ++i) {
#pragma unroll
        for (int h = 0; h < 2; ++h) {
            const int gm = m0 + wm * 64 + i * 16 + g + h * 8;
            if (gm < Mc) {
                float* rowp = out + (size_t)g_idx[gm] * H_DIM;
#pragma unroll
                for (int j = 0; j < 4; ++j) {
                    const int gn = n0 + wn * 32 + j * 8 + c * 2;
                    *(float2*)(rowp + gn) =
                        make_float2(acc[i][j][h * 2 + 0], acc[i][j][h * 2 + 1]);
                }
            }
        }
    }
}

// ---------------------------------------------------------------------------
extern "C" void kernel_launch(void* const* d_in, const int* in_sizes, int n_in,
                              void* d_out, int out_size)
{
    const float* hidden = (const float*)d_in[0];
    const float* w_up   = (const float*)d_in[1];
    const float* w_gate = (const float*)d_in[2];
    const float* w_down = (const float*)d_in[3];
    const int*   mask   = (const int*)d_in[4];
    float* out = (float*)d_out;

    const int SMEM_F = S * STG_F * sizeof(__half);   // 221184
    const int SMEM_D = S * STG_D * sizeof(__half);   // 221184
    cudaFuncSetAttribute(fused_upgate_kernel, cudaFuncAttributeMaxDynamicSharedMemorySize, SMEM_F);
    cudaFuncSetAttribute(down_kernel,         cudaFuncAttributeMaxDynamicSharedMemorySize, SMEM_D);

    void *d_wu, *d_wg, *d_wd;
    cudaGetSymbolAddress(&d_wu, g_wu);
    cudaGetSymbolAddress(&d_wg, g_wg);
    cudaGetSymbolAddress(&d_wd, g_wd);

    compact_kernel<<<1, 1024>>>(mask);
    gather_kernel<<<NTOK, 256>>>((const float4*)hidden);

    const int wg_groups = (I_DIM * H_DIM) / 8;
    cvt3_kernel<<<8192, 256>>>((const float4*)w_up,   (uint4*)d_wu,
                               (const float4*)w_gate, (uint4*)d_wg,
                               (const float4*)w_down, (uint4*)d_wd, wg_groups);

    zero_rows_kernel<<<NTOK, 256>>>((float4*)out);

    dim3 blk(NTHREADS);
    fused_upgate_kernel<<<dim3(NTOK / 128, I_DIM / 128), blk, SMEM_F>>>();
    down_kernel<<<dim3(NTOK / 256, H_DIM / 128), blk, SMEM_D>>>(out);
}